// round 1
// baseline (speedup 1.0000x reference)
#include <cuda_runtime.h>

#define NBLK    144
#define TPB     256
#define TSTEPS  128
#define BB      256
#define HH      256
#define INF     128
#define OUTF    128
#define G3H     768     // 3*H
#define M3B     768     // 3*B rows of the recurrent state matrix

// ---------------- device scratch (no allocations allowed) ----------------
__device__ float g_gx[(size_t)TSTEPS * BB * G3H];   // precomputed x@Wx+bx, [t][b][3H]  (~96MB)
__device__ float g_G [M3B * G3H];                   // per-step gh = h@Wh  (768x768)
__device__ float g_h [M3B * HH];                    // recurrent state, rows m=c*256+b
__device__ unsigned int          g_barcnt = 0;
__device__ volatile unsigned int g_bargen = 0;

// ---------------- helpers ----------------
__device__ __forceinline__ unsigned long long pack2(float v) {
    unsigned long long r; unsigned int u = __float_as_uint(v);
    asm("mov.b64 %0, {%1, %2};" : "=l"(r) : "r"(u), "r"(u));
    return r;
}
__device__ __forceinline__ void ffma2(unsigned long long& c, unsigned long long a, unsigned long long b) {
    asm("fma.rn.f32x2 %0, %1, %2, %0;" : "+l"(c) : "l"(a), "l"(b));
}
union F4U { unsigned long long u[2]; float4 f; };

__device__ __forceinline__ float sigm(float x) {
    return 1.0f / (1.0f + __expf(-x));
}
__device__ __forceinline__ float tanh_fast(float x) {
    float ax = fabsf(x);
    float e  = __expf(-2.0f * ax);               // in (0,1], no overflow
    float t  = 1.0f - 2.0f * e * __frcp_rn(1.0f + e);
    return copysignf(t, x);
}

__device__ __forceinline__ void gbar() {
    __syncthreads();
    if (threadIdx.x == 0) {
        unsigned int gen = g_bargen;
        __threadfence();                          // release my stores
        if (atomicAdd(&g_barcnt, 1u) == NBLK - 1) {
            g_barcnt = 0;
            __threadfence();
            g_bargen = gen + 1;                   // release all
        } else {
            while (g_bargen == gen) { }
            __threadfence();                      // acquire: gpu-scope fence flushes L1 (CCTL.IVALL)
        }
    }
    __syncthreads();
}

// ---------------- phase 1: GX = X @ Wx + bx  (fully parallel) ----------------
// rows m = t*256 + b  (m in [0, 32768)), cols 768, K = 128
__global__ void __launch_bounds__(TPB) gx_kernel(const float* __restrict__ x,
                                                 const float* __restrict__ Wx,
                                                 const float* __restrict__ bx) {
    __shared__ float sX[64 * 68];   // [kk][row], pad 4
    __shared__ float sW[64 * 64];   // [kk][n]
    const int tid = threadIdx.x;
    const int m0 = blockIdx.x * 64;
    const int n0 = blockIdx.y * 64;
    const int tyr = (tid >> 4) << 2;
    const int txc = (tid & 15) << 2;

    unsigned long long acc[4][2];
#pragma unroll
    for (int i = 0; i < 4; ++i) { acc[i][0] = 0ULL; acc[i][1] = 0ULL; }

    for (int k0 = 0; k0 < INF; k0 += 64) {
        __syncthreads();
#pragma unroll
        for (int i = tid; i < 64 * 64; i += TPB) {
            int rl = i >> 6, kk = i & 63;
            int m = m0 + rl;
            int tt = m >> 8, bb2 = m & 255;
            sX[kk * 68 + rl] = x[bb2 * (TSTEPS * INF) + tt * INF + k0 + kk];
        }
#pragma unroll
        for (int i = tid; i < 64 * 64; i += TPB) {
            int kk = i >> 6, n = i & 63;
            sW[kk * 64 + n] = Wx[(k0 + kk) * G3H + n0 + n];
        }
        __syncthreads();
#pragma unroll 8
        for (int kk = 0; kk < 64; ++kk) {
            float4 a4 = *(const float4*)(sX + kk * 68 + tyr);
            ulonglong2 bv = *(const ulonglong2*)(sW + kk * 64 + txc);
            unsigned long long a;
            a = pack2(a4.x); ffma2(acc[0][0], a, bv.x); ffma2(acc[0][1], a, bv.y);
            a = pack2(a4.y); ffma2(acc[1][0], a, bv.x); ffma2(acc[1][1], a, bv.y);
            a = pack2(a4.z); ffma2(acc[2][0], a, bv.x); ffma2(acc[2][1], a, bv.y);
            a = pack2(a4.w); ffma2(acc[3][0], a, bv.x); ffma2(acc[3][1], a, bv.y);
        }
    }
    float4 bx4 = *(const float4*)(bx + n0 + txc);
#pragma unroll
    for (int i = 0; i < 4; ++i) {
        F4U cv; cv.u[0] = acc[i][0]; cv.u[1] = acc[i][1];
        cv.f.x += bx4.x; cv.f.y += bx4.y; cv.f.z += bx4.z; cv.f.w += bx4.w;
        *(float4*)(g_gx + (size_t)(m0 + tyr + i) * G3H + n0 + txc) = cv.f;
    }
}

// ---------------- phase 2: persistent scan kernel ----------------
// grid = 144 blocks (12 row-bands x 12 col-tiles), 256 threads, ~132KB dyn smem
__global__ void __launch_bounds__(TPB, 1) cru_persistent(const float* __restrict__ hid,
                                                         const float* __restrict__ Wh,
                                                         const float* __restrict__ bh,
                                                         const float* __restrict__ Wf,
                                                         const float* __restrict__ bf,
                                                         float* __restrict__ out) {
    extern __shared__ float smem[];
    float* sWh = smem;               // [256][64]  persistent Wh column slice
    float* sA  = smem + 256 * 64;    // [256][68]  h band (transposed), pad 4

    const int tid = threadIdx.x;
    const int bid = blockIdx.x;
    const int tm = bid / 12, tn = bid % 12;
    const int rm0 = tm * 64;         // row band  [rm0, rm0+64) of m = c*256+b
    const int cn0 = tn * 64;         // col tile  [cn0, cn0+64) of 3H
    const int tyr = (tid >> 4) << 2;
    const int txc = (tid & 15) << 2;
    const int gtid = bid * TPB + tid;

    // load persistent Wh slice: sWh[k][n] = Wh[k][cn0+n]
#pragma unroll
    for (int i = tid; i < 256 * 64; i += TPB)
        sWh[i] = Wh[(i >> 6) * G3H + cn0 + (i & 63)];

    // init g_h from hid_state (layout (1,3,B,H) == m*H+k)
    for (int i = gtid; i < M3B * HH; i += NBLK * TPB)
        __stcg(&g_h[i], hid[i]);

    // hoist biases for the update column this thread owns (k = tid)
    const float bhr = bh[tid], bhz = bh[256 + tid], bhn = bh[512 + tid];

    gbar();

    for (int t = 0; t < TSTEPS; ++t) {
        // ---- load A band (h) into smem, transposed ----
#pragma unroll 4
        for (int i = tid; i < 64 * 256; i += TPB) {
            int rl = i >> 8, kk = i & 255;                   // kk == tid
            sA[kk * 68 + rl] = __ldcg(&g_h[(rm0 + rl) * HH + kk]);
        }
        __syncthreads();

        // ---- GEMM: G tile = h_band @ Wh_slice ----
        unsigned long long acc[4][2];
#pragma unroll
        for (int i = 0; i < 4; ++i) { acc[i][0] = 0ULL; acc[i][1] = 0ULL; }
#pragma unroll 8
        for (int kk = 0; kk < 256; ++kk) {
            float4 a4 = *(const float4*)(sA + kk * 68 + tyr);
            ulonglong2 bv = *(const ulonglong2*)(sWh + kk * 64 + txc);
            unsigned long long a;
            a = pack2(a4.x); ffma2(acc[0][0], a, bv.x); ffma2(acc[0][1], a, bv.y);
            a = pack2(a4.y); ffma2(acc[1][0], a, bv.x); ffma2(acc[1][1], a, bv.y);
            a = pack2(a4.z); ffma2(acc[2][0], a, bv.x); ffma2(acc[2][1], a, bv.y);
            a = pack2(a4.w); ffma2(acc[3][0], a, bv.x); ffma2(acc[3][1], a, bv.y);
        }
#pragma unroll
        for (int i = 0; i < 4; ++i) {
            F4U cv; cv.u[0] = acc[i][0]; cv.u[1] = acc[i][1];
            *(float4*)(g_G + (rm0 + tyr + i) * G3H + cn0 + txc) = cv.f;
        }

        gbar();   // G complete grid-wide

        // ---- elementwise gate update: h <- n + z*(h-n), partitioned grid-wide ----
        const float* gxb = g_gx + (size_t)t * BB * G3H;
        for (int e = gtid; e < M3B * HH; e += NBLK * TPB) {  // k = e&255 == tid
            int m = e >> 8;
            int b = m & 255;
            const float* gxp = gxb + b * G3H;
            const float* Gm  = g_G + m * G3H;
            float hr = __ldcg(Gm + tid)       + bhr;
            float hz = __ldcg(Gm + 256 + tid) + bhz;
            float hn = __ldcg(Gm + 512 + tid) + bhn;
            float r = sigm(gxp[tid]       + hr);
            float z = sigm(gxp[256 + tid] + hz);
            float n = tanh_fast(gxp[512 + tid] + r * hn);
            float* hp = g_h + m * HH + tid;
            float ho = __ldcg(hp);
            __stcg(hp, n + z * (ho - n));
        }

        gbar();   // h complete grid-wide
    }

    // ---------------- output head ----------------
    if (bid < 128) {
        // out[b][o] = elu( sum_k (h0+h1+h2)[b][k] * Wf[k][o] + bf[o] )
        int rb = (bid << 1) + (tid >> 7);
        int o  = tid & 127;
        float acc = bf[o];
        const float* h0 = g_h + rb * HH;
        const float* h1 = g_h + (256 + rb) * HH;
        const float* h2 = g_h + (512 + rb) * HH;
#pragma unroll 4
        for (int k = 0; k < HH; ++k) {
            float s = __ldcg(h0 + k) + __ldcg(h1 + k) + __ldcg(h2 + k);
            acc = fmaf(s, Wf[k * OUTF + o], acc);
        }
        out[rb * OUTF + o] = (acc > 0.0f) ? acc : expm1f(acc);
    } else if (bid < 131) {
        // feature[c][k] = mean_b hT[c][b][k]
        int c = bid - 128;
        float acc = 0.0f;
#pragma unroll 4
        for (int b2 = 0; b2 < BB; ++b2)
            acc += __ldcg(&g_h[(c * 256 + b2) * HH + tid]);
        out[BB * OUTF + c * HH + tid] = acc * (1.0f / 256.0f);
    }
}

// ---------------- launch ----------------
extern "C" void kernel_launch(void* const* d_in, const int* in_sizes, int n_in,
                              void* d_out, int out_size) {
    const float* x   = (const float*)d_in[0];
    const float* hid = (const float*)d_in[1];
    const float* Wx  = (const float*)d_in[2];
    const float* bx  = (const float*)d_in[3];
    const float* Wh  = (const float*)d_in[4];
    const float* bh  = (const float*)d_in[5];
    const float* Wf  = (const float*)d_in[6];
    const float* bf  = (const float*)d_in[7];
    float* out = (float*)d_out;

    const int smem_p = (256 * 64 + 256 * 68) * (int)sizeof(float);   // 135168 B
    cudaFuncSetAttribute(cru_persistent, cudaFuncAttributeMaxDynamicSharedMemorySize, smem_p);

    gx_kernel<<<dim3(512, 12), TPB>>>(x, Wx, bx);
    cru_persistent<<<NBLK, TPB, smem_p>>>(hid, Wh, bh, Wf, bf, out);
}

// round 2
// speedup vs baseline: 1.6140x; 1.6140x over previous
#include <cuda_runtime.h>

#define NBLK    144
#define TPB     256
#define TSTEPS  128
#define BB      256
#define HH      256
#define INF     128
#define OUTF    128
#define G3H     768     // 3*H
#define M3B     768     // 3*B rows of the recurrent state matrix
#define APITCH  66      // sA pitch (floats): 2-way store conflicts, float2-aligned reads

// ---------------- device scratch (no allocations allowed) ----------------
__device__ float g_gx[(size_t)TSTEPS * BB * G3H];   // precomputed x@Wx+bx, [t][b][3H]
__device__ float g_G [M3B * G3H];                   // per-step gh = h@Wh  (768x768)
__device__ float g_h [M3B * HH];                    // recurrent state, rows m=c*256+b
__device__ unsigned int          g_barcnt = 0;
__device__ volatile unsigned int g_bargen = 0;

// ---------------- helpers ----------------
__device__ __forceinline__ unsigned long long pack2(float v) {
    unsigned long long r; unsigned int u = __float_as_uint(v);
    asm("mov.b64 %0, {%1, %2};" : "=l"(r) : "r"(u), "r"(u));
    return r;
}
__device__ __forceinline__ void ffma2(unsigned long long& c, unsigned long long a, unsigned long long b) {
    asm("fma.rn.f32x2 %0, %1, %2, %0;" : "+l"(c) : "l"(a), "l"(b));
}
union F4U { unsigned long long u[2]; float4 f; };

__device__ __forceinline__ float sigm(float x) {
    float e = __expf(-x);
    return __fdividef(1.0f, 1.0f + e);
}
__device__ __forceinline__ float tanh_fast(float x) {
    float ax = fabsf(x);
    float e  = __expf(-2.0f * ax);               // in (0,1], no overflow
    float t  = 1.0f - __fdividef(2.0f * e, 1.0f + e);
    return copysignf(t, x);
}

// full barrier (arrive + wait fused)
__device__ __forceinline__ void gbar() {
    __syncthreads();
    if (threadIdx.x == 0) {
        unsigned int gen = g_bargen;
        __threadfence();                          // release my stores
        if (atomicAdd(&g_barcnt, 1u) == NBLK - 1) {
            g_barcnt = 0;
            __threadfence();
            g_bargen = gen + 1;                   // release all
        } else {
            while (g_bargen == gen) { }
            __threadfence();                      // acquire
        }
    }
    __syncthreads();
}

// ---------------- phase 1: GX = X @ Wx + bx  (fully parallel) ----------------
__global__ void __launch_bounds__(TPB) gx_kernel(const float* __restrict__ x,
                                                 const float* __restrict__ Wx,
                                                 const float* __restrict__ bx) {
    __shared__ float sX[64 * 68];   // [kk][row], pad 4
    __shared__ float sW[64 * 64];   // [kk][n]
    const int tid = threadIdx.x;
    const int m0 = blockIdx.x * 64;
    const int n0 = blockIdx.y * 64;
    const int tyr = (tid >> 4) << 2;
    const int txc = (tid & 15) << 2;

    unsigned long long acc[4][2];
#pragma unroll
    for (int i = 0; i < 4; ++i) { acc[i][0] = 0ULL; acc[i][1] = 0ULL; }

    for (int k0 = 0; k0 < INF; k0 += 64) {
        __syncthreads();
#pragma unroll
        for (int i = tid; i < 64 * 64; i += TPB) {
            int rl = i >> 6, kk = i & 63;
            int m = m0 + rl;
            int tt = m >> 8, bb2 = m & 255;
            sX[kk * 68 + rl] = x[bb2 * (TSTEPS * INF) + tt * INF + k0 + kk];
        }
#pragma unroll
        for (int i = tid; i < 64 * 64; i += TPB) {
            int kk = i >> 6, n = i & 63;
            sW[kk * 64 + n] = Wx[(k0 + kk) * G3H + n0 + n];
        }
        __syncthreads();
#pragma unroll 8
        for (int kk = 0; kk < 64; ++kk) {
            float4 a4 = *(const float4*)(sX + kk * 68 + tyr);
            ulonglong2 bv = *(const ulonglong2*)(sW + kk * 64 + txc);
            unsigned long long a;
            a = pack2(a4.x); ffma2(acc[0][0], a, bv.x); ffma2(acc[0][1], a, bv.y);
            a = pack2(a4.y); ffma2(acc[1][0], a, bv.x); ffma2(acc[1][1], a, bv.y);
            a = pack2(a4.z); ffma2(acc[2][0], a, bv.x); ffma2(acc[2][1], a, bv.y);
            a = pack2(a4.w); ffma2(acc[3][0], a, bv.x); ffma2(acc[3][1], a, bv.y);
        }
    }
    float4 bx4 = *(const float4*)(bx + n0 + txc);
#pragma unroll
    for (int i = 0; i < 4; ++i) {
        F4U cv; cv.u[0] = acc[i][0]; cv.u[1] = acc[i][1];
        cv.f.x += bx4.x; cv.f.y += bx4.y; cv.f.z += bx4.z; cv.f.w += bx4.w;
        *(float4*)(g_gx + (size_t)(m0 + tyr + i) * G3H + n0 + txc) = cv.f;
    }
}

// ---------------- phase 2: persistent scan kernel ----------------
// grid = 144 blocks (12 row-bands x 12 col-tiles), 256 threads
// smem: sWh [256][64] + sA [256][66] + sGx [6][768]  = 151552 B
__global__ void __launch_bounds__(TPB, 1) cru_persistent(const float* __restrict__ hid,
                                                         const float* __restrict__ Wh,
                                                         const float* __restrict__ bh,
                                                         const float* __restrict__ Wf,
                                                         const float* __restrict__ bf,
                                                         float* __restrict__ out) {
    extern __shared__ float smem[];
    float* sWh = smem;                       // [256][64]  persistent Wh slice
    float* sA  = smem + 256 * 64;            // [256][APITCH] h band (transposed)
    float* sGx = smem + 256 * 64 + 256 * APITCH;  // [6][768] prefetched gx rows

    const int tid = threadIdx.x;
    const int bid = blockIdx.x;
    const int tm = bid / 12, tn = bid % 12;
    const int rm0 = tm * 64;
    const int cn0 = tn * 64;
    const int tyr = (tid >> 4) << 2;
    const int txc = (tid & 15) << 2;
    const int gtid = bid * TPB + tid;

    // persistent Wh slice
#pragma unroll
    for (int i = tid; i < 256 * 64; i += TPB)
        sWh[i] = Wh[(i >> 6) * G3H + cn0 + (i & 63)];

    // init g_h from hid_state
    for (int i = gtid; i < M3B * HH; i += NBLK * TPB)
        __stcg(&g_h[i], hid[i]);

    const float bhr = bh[tid], bhz = bh[256 + tid], bhn = bh[512 + tid];

    gbar();

    unsigned int bgen;   // thread0's barrier generation (lives in register)

    for (int t = 0; t < TSTEPS; ++t) {
        // ---- fill sA (h band, transposed), batched loads for MLP ----
        {
            const float* hrow = g_h + rm0 * HH + tid;   // column tid of the band
            float* sacol = sA + tid * APITCH;
#pragma unroll
            for (int c = 0; c < 4; ++c) {
                float v[16];
#pragma unroll
                for (int j = 0; j < 16; ++j) v[j] = __ldcg(hrow + (c * 16 + j) * HH);
#pragma unroll
                for (int j = 0; j < 16; ++j) sacol[c * 16 + j] = v[j];
            }
        }
        __syncthreads();

        // ---- GEMM: G tile = h_band @ Wh_slice ----
        unsigned long long acc[4][2];
#pragma unroll
        for (int i = 0; i < 4; ++i) { acc[i][0] = 0ULL; acc[i][1] = 0ULL; }
#pragma unroll 8
        for (int kk = 0; kk < 256; ++kk) {
            float2 a01 = *(const float2*)(sA + kk * APITCH + tyr);
            float2 a23 = *(const float2*)(sA + kk * APITCH + tyr + 2);
            ulonglong2 bv = *(const ulonglong2*)(sWh + kk * 64 + txc);
            unsigned long long a;
            a = pack2(a01.x); ffma2(acc[0][0], a, bv.x); ffma2(acc[0][1], a, bv.y);
            a = pack2(a01.y); ffma2(acc[1][0], a, bv.x); ffma2(acc[1][1], a, bv.y);
            a = pack2(a23.x); ffma2(acc[2][0], a, bv.x); ffma2(acc[2][1], a, bv.y);
            a = pack2(a23.y); ffma2(acc[3][0], a, bv.x); ffma2(acc[3][1], a, bv.y);
        }
#pragma unroll
        for (int i = 0; i < 4; ++i) {
            F4U cv; cv.u[0] = acc[i][0]; cv.u[1] = acc[i][1];
            *(float4*)(g_G + (rm0 + tyr + i) * G3H + cn0 + txc) = cv.f;
        }

        // ---- barrier 1 (G ready), with gx[t] prefetch in the arrive->wait gap ----
        __syncthreads();
        if (tid == 0) {
            bgen = g_bargen;
            __threadfence();
            if (atomicAdd(&g_barcnt, 1u) == NBLK - 1) {
                g_barcnt = 0;
                __threadfence();
                g_bargen = bgen + 1;
            }
        }
        // prefetch gx rows this block needs for the update (DRAM latency overlapped)
        {
            const float* gxb = g_gx + (size_t)t * BB * G3H;
#pragma unroll
            for (int i = 0; i < 6; ++i) {
                int m = bid + 144 * i;
                if (m < M3B) {
                    int b = m & 255;
                    const float* src = gxb + (size_t)b * G3H;
                    sGx[i * G3H + tid]       = __ldcg(src + tid);
                    sGx[i * G3H + 256 + tid] = __ldcg(src + 256 + tid);
                    sGx[i * G3H + 512 + tid] = __ldcg(src + 512 + tid);
                }
            }
        }
        if (tid == 0) {
            while (g_bargen == bgen) { }
            __threadfence();
        }
        __syncthreads();

        // ---- elementwise gate update: h <- n + z*(h-n) ----
#pragma unroll
        for (int i = 0; i < 6; ++i) {
            int m = bid + 144 * i;
            if (m < M3B) {
                const float* Gm = g_G + m * G3H;
                float hr = __ldcg(Gm + tid)       + bhr;
                float hz = __ldcg(Gm + 256 + tid) + bhz;
                float hn = __ldcg(Gm + 512 + tid) + bhn;
                float* hp = g_h + m * HH + tid;
                float ho = __ldcg(hp);
                float r = sigm(sGx[i * G3H + tid]       + hr);
                float z = sigm(sGx[i * G3H + 256 + tid] + hz);
                float n = tanh_fast(sGx[i * G3H + 512 + tid] + r * hn);
                __stcg(hp, n + z * (ho - n));
            }
        }

        gbar();   // h complete grid-wide
    }

    // ---------------- output head ----------------
    if (bid < 128) {
        int rb = (bid << 1) + (tid >> 7);
        int o  = tid & 127;
        float acc = bf[o];
        const float* h0 = g_h + rb * HH;
        const float* h1 = g_h + (256 + rb) * HH;
        const float* h2 = g_h + (512 + rb) * HH;
#pragma unroll 8
        for (int k = 0; k < HH; ++k) {
            float s = __ldcg(h0 + k) + __ldcg(h1 + k) + __ldcg(h2 + k);
            acc = fmaf(s, Wf[k * OUTF + o], acc);
        }
        out[rb * OUTF + o] = (acc > 0.0f) ? acc : expm1f(acc);
    } else if (bid < 131) {
        int c = bid - 128;
        float acc = 0.0f;
#pragma unroll 8
        for (int b2 = 0; b2 < BB; ++b2)
            acc += __ldcg(&g_h[(c * 256 + b2) * HH + tid]);
        out[BB * OUTF + c * HH + tid] = acc * (1.0f / 256.0f);
    }
}

// ---------------- launch ----------------
extern "C" void kernel_launch(void* const* d_in, const int* in_sizes, int n_in,
                              void* d_out, int out_size) {
    const float* x   = (const float*)d_in[0];
    const float* hid = (const float*)d_in[1];
    const float* Wx  = (const float*)d_in[2];
    const float* bx  = (const float*)d_in[3];
    const float* Wh  = (const float*)d_in[4];
    const float* bh  = (const float*)d_in[5];
    const float* Wf  = (const float*)d_in[6];
    const float* bf  = (const float*)d_in[7];
    float* out = (float*)d_out;

    const int smem_p = (256 * 64 + 256 * APITCH + 6 * G3H) * (int)sizeof(float); // 151552
    cudaFuncSetAttribute(cru_persistent, cudaFuncAttributeMaxDynamicSharedMemorySize, smem_p);

    gx_kernel<<<dim3(512, 12), TPB>>>(x, Wx, bx);
    cru_persistent<<<NBLK, TPB, smem_p>>>(hid, Wh, bh, Wf, bf, out);
}

// round 3
// speedup vs baseline: 1.8400x; 1.1400x over previous
#include <cuda_runtime.h>

#define NBLK    128
#define TPB     256
#define TSTEPS  128
#define BB      256
#define HH      256
#define INF     128
#define OUTF    128
#define G3H     768
#define M3B     768
#define AP      260      // sA row pitch (floats)
#define RBAND   48       // rows per band
#define CT      32       // gate-cols per tile (actual cols = 3*CT = 96)

typedef unsigned long long ull;

// ---------------- device scratch ----------------
__device__ float g_gx[(size_t)TSTEPS * BB * G3H];   // x@Wx+bx, [t][b][3H]
__device__ float g_h0[M3B * HH];                    // ping-pong recurrent state
__device__ float g_h1[M3B * HH];
__device__ unsigned int          g_barcnt = 0;
__device__ volatile unsigned int g_bargen = 0;

// ---------------- helpers ----------------
__device__ __forceinline__ ull pack2(float v) {
    ull r; unsigned int u = __float_as_uint(v);
    asm("mov.b64 %0, {%1, %2};" : "=l"(r) : "r"(u), "r"(u));
    return r;
}
__device__ __forceinline__ void ffma2(ull& c, ull a, ull b) {
    asm("fma.rn.f32x2 %0, %1, %2, %0;" : "+l"(c) : "l"(a), "l"(b));
}
__device__ __forceinline__ float2 unpk(ull v) {
    float2 r; asm("mov.b64 {%0, %1}, %2;" : "=f"(r.x), "=f"(r.y) : "l"(v));
    return r;
}
union F4U { ull u[2]; float4 f; };

__device__ __forceinline__ float sigm(float x) {
    float e = __expf(-x);
    return __fdividef(1.0f, 1.0f + e);
}
__device__ __forceinline__ float tanh_fast(float x) {
    float ax = fabsf(x);
    float e  = __expf(-2.0f * ax);
    float t  = 1.0f - __fdividef(2.0f * e, 1.0f + e);
    return copysignf(t, x);
}
__device__ __forceinline__ void cpa16(unsigned int saddr, const void* gptr) {
    asm volatile("cp.async.ca.shared.global [%0], [%1], 16;" :: "r"(saddr), "l"(gptr) : "memory");
}

__device__ __forceinline__ void gbar() {
    __syncthreads();
    if (threadIdx.x == 0) {
        unsigned int gen = g_bargen;
        __threadfence();
        if (atomicAdd(&g_barcnt, 1u) == NBLK - 1) {
            g_barcnt = 0;
            __threadfence();
            g_bargen = gen + 1;
        } else {
            while (g_bargen == gen) { }
            __threadfence();
        }
    }
    __syncthreads();
}

// ---------------- phase 1: GX = X @ Wx + bx ----------------
__global__ void __launch_bounds__(TPB) gx_kernel(const float* __restrict__ x,
                                                 const float* __restrict__ Wx,
                                                 const float* __restrict__ bx) {
    __shared__ float sX[64 * 68];
    __shared__ float sW[64 * 64];
    const int tid = threadIdx.x;
    const int m0 = blockIdx.x * 64;
    const int n0 = blockIdx.y * 64;
    const int tyr = (tid >> 4) << 2;
    const int txc = (tid & 15) << 2;

    ull acc[4][2];
#pragma unroll
    for (int i = 0; i < 4; ++i) { acc[i][0] = 0ULL; acc[i][1] = 0ULL; }

    for (int k0 = 0; k0 < INF; k0 += 64) {
        __syncthreads();
#pragma unroll
        for (int i = tid; i < 64 * 64; i += TPB) {
            int rl = i >> 6, kk = i & 63;
            int m = m0 + rl;
            int tt = m >> 8, bb2 = m & 255;
            sX[kk * 68 + rl] = x[bb2 * (TSTEPS * INF) + tt * INF + k0 + kk];
        }
#pragma unroll
        for (int i = tid; i < 64 * 64; i += TPB) {
            int kk = i >> 6, n = i & 63;
            sW[kk * 64 + n] = Wx[(k0 + kk) * G3H + n0 + n];
        }
        __syncthreads();
#pragma unroll 8
        for (int kk = 0; kk < 64; ++kk) {
            float4 a4 = *(const float4*)(sX + kk * 68 + tyr);
            ulonglong2 bv = *(const ulonglong2*)(sW + kk * 64 + txc);
            ull a;
            a = pack2(a4.x); ffma2(acc[0][0], a, bv.x); ffma2(acc[0][1], a, bv.y);
            a = pack2(a4.y); ffma2(acc[1][0], a, bv.x); ffma2(acc[1][1], a, bv.y);
            a = pack2(a4.z); ffma2(acc[2][0], a, bv.x); ffma2(acc[2][1], a, bv.y);
            a = pack2(a4.w); ffma2(acc[3][0], a, bv.x); ffma2(acc[3][1], a, bv.y);
        }
    }
    float4 bx4 = *(const float4*)(bx + n0 + txc);
#pragma unroll
    for (int i = 0; i < 4; ++i) {
        F4U cv; cv.u[0] = acc[i][0]; cv.u[1] = acc[i][1];
        cv.f.x += bx4.x; cv.f.y += bx4.y; cv.f.z += bx4.z; cv.f.w += bx4.w;
        *(float4*)(g_gx + (size_t)(m0 + tyr + i) * G3H + n0 + txc) = cv.f;
    }
}

// ---------------- phase 2: persistent scan ----------------
// 128 blocks = 16 row-bands(48) x 8 col-tiles(32 gate-cols -> 96 actual cols).
// Each thread owns 3 rows x 2 gate-cols -> full (r,z,n) triple in registers.
// smem: sWh[256][96] + sA[48][260] + sGx[48][96] = 166656 B
__global__ void __launch_bounds__(TPB, 1) cru_persistent(const float* __restrict__ hid,
                                                         const float* __restrict__ Wh,
                                                         const float* __restrict__ bh,
                                                         const float* __restrict__ Wf,
                                                         const float* __restrict__ bf,
                                                         float* __restrict__ out) {
    extern __shared__ float smem[];
    float* sWh = smem;                 // [256][96]
    float* sA  = smem + 24576;         // [48][AP]
    float* sGx = smem + 24576 + RBAND * AP;  // [48][96]

    const int tid = threadIdx.x;
    const int bid = blockIdx.x;
    const int band = bid >> 3, ctile = bid & 7;
    const int rm0 = band * RBAND;
    const int k0  = ctile * CT;
    const int ty = tid >> 4, tx = tid & 15;
    const int ty3 = ty * 3, tx2 = tx * 2;
    const int gtid = bid * TPB + tid;
    const unsigned int sGx_b = (unsigned int)__cvta_generic_to_shared(sGx);

    // persistent Wh slice: sWh[kk][seg*32+c] = Wh[kk][seg*256 + k0 + c]
    for (int i = tid; i < 96 * 256; i += TPB) {
        int kk = i / 96, c = i - kk * 96;
        int seg = c >> 5, cc = c & 31;
        sWh[i] = Wh[kk * G3H + seg * HH + k0 + cc];
    }
    // init h buffer 0
    for (int i = gtid; i < M3B * HH; i += NBLK * TPB)
        __stcg(&g_h0[i], hid[i]);

    // per-thread gate biases (k = k0+tx2, k0+tx2+1)
    const float bhr0 = bh[k0 + tx2],          bhr1 = bh[k0 + tx2 + 1];
    const float bhz0 = bh[HH + k0 + tx2],     bhz1 = bh[HH + k0 + tx2 + 1];
    const float bhn0 = bh[2 * HH + k0 + tx2], bhn1 = bh[2 * HH + k0 + tx2 + 1];

    gbar();

    for (int t = 0; t < TSTEPS; ++t) {
        const float* hin  = (t & 1) ? g_h1 : g_h0;
        float*       hout = (t & 1) ? g_h0 : g_h1;

        // ---- async prefetch gx[t] rows for this block's (rows x 96 cols) ----
        const float* gxb = g_gx + (size_t)t * BB * G3H;
#pragma unroll
        for (int c = tid; c < 1152; c += TPB) {       // 1152 x 16B chunks
            int row = c / 24;
            int q = c - row * 24;
            int seg = q >> 3;
            int f0 = (q & 7) << 2;
            int b = (rm0 + row) & 255;
            cpa16(sGx_b + (unsigned)((row * 96 + seg * 32 + f0) << 2),
                  gxb + (size_t)b * G3H + seg * HH + k0 + f0);
        }
        asm volatile("cp.async.commit_group;" ::: "memory");

        // ---- old h values for this thread's outputs (registers) ----
        float2 hold[3];
#pragma unroll
        for (int r = 0; r < 3; ++r)
            hold[r] = __ldcg((const float2*)(hin + (rm0 + ty3 + r) * HH + k0 + tx2));

        // ---- sA fill: sA[row][kk] = h[rm0+row][kk], kk = tid ----
#pragma unroll
        for (int c = 0; c < 3; ++c) {
            float v[16];
#pragma unroll
            for (int j = 0; j < 16; ++j) v[j] = __ldcg(&hin[(rm0 + c * 16 + j) * HH + tid]);
#pragma unroll
            for (int j = 0; j < 16; ++j) sA[(c * 16 + j) * AP + tid] = v[j];
        }
        __syncthreads();

        // ---- GEMM: acc[r][g] = sum_k h[row_r][k] * Wh[k][gate g, cols tx2..tx2+1] ----
        ull acc[3][3];
#pragma unroll
        for (int r = 0; r < 3; ++r) { acc[r][0] = 0ULL; acc[r][1] = 0ULL; acc[r][2] = 0ULL; }
        const float* saty = sA + ty3 * AP;
#pragma unroll 4
        for (int kk = 0; kk < 256; kk += 2) {
            float2 a0 = *(const float2*)(saty + kk);
            float2 a1 = *(const float2*)(saty + AP + kk);
            float2 a2 = *(const float2*)(saty + 2 * AP + kk);
            const ull* w0 = (const ull*)(sWh + kk * 96 + tx2);
            const ull* w1 = (const ull*)(sWh + (kk + 1) * 96 + tx2);
            ull bR0 = w0[0], bZ0 = w0[16], bN0 = w0[32];
            ull bR1 = w1[0], bZ1 = w1[16], bN1 = w1[32];
            ull a;
            a = pack2(a0.x); ffma2(acc[0][0], a, bR0); ffma2(acc[0][1], a, bZ0); ffma2(acc[0][2], a, bN0);
            a = pack2(a1.x); ffma2(acc[1][0], a, bR0); ffma2(acc[1][1], a, bZ0); ffma2(acc[1][2], a, bN0);
            a = pack2(a2.x); ffma2(acc[2][0], a, bR0); ffma2(acc[2][1], a, bZ0); ffma2(acc[2][2], a, bN0);
            a = pack2(a0.y); ffma2(acc[0][0], a, bR1); ffma2(acc[0][1], a, bZ1); ffma2(acc[0][2], a, bN1);
            a = pack2(a1.y); ffma2(acc[1][0], a, bR1); ffma2(acc[1][1], a, bZ1); ffma2(acc[1][2], a, bN1);
            a = pack2(a2.y); ffma2(acc[2][0], a, bR1); ffma2(acc[2][1], a, bZ1); ffma2(acc[2][2], a, bN1);
        }

        asm volatile("cp.async.wait_group 0;" ::: "memory");
        __syncthreads();   // sGx visible to all

        // ---- gate update entirely in registers ----
#pragma unroll
        for (int r = 0; r < 3; ++r) {
            float2 Gr = unpk(acc[r][0]);
            float2 Gz = unpk(acc[r][1]);
            float2 Gn = unpk(acc[r][2]);
            const float* gp = sGx + (ty3 + r) * 96 + tx2;
            float R0 = sigm(gp[0]  + Gr.x + bhr0);
            float R1 = sigm(gp[1]  + Gr.y + bhr1);
            float Z0 = sigm(gp[32] + Gz.x + bhz0);
            float Z1 = sigm(gp[33] + Gz.y + bhz1);
            float N0 = tanh_fast(gp[64] + R0 * (Gn.x + bhn0));
            float N1 = tanh_fast(gp[65] + R1 * (Gn.y + bhn1));
            float2 hn;
            hn.x = N0 + Z0 * (hold[r].x - N0);
            hn.y = N1 + Z1 * (hold[r].y - N1);
            __stcg((float2*)(hout + (rm0 + ty3 + r) * HH + k0 + tx2), hn);
        }

        gbar();   // single barrier per step
    }

    // ---------------- output head (final h is in g_h0: t=127 writes g_h0) ----------------
    {
        int rb = (bid << 1) + (tid >> 7);
        int o  = tid & 127;
        float acc = bf[o];
        const float* h0 = g_h0 + rb * HH;
        const float* h1 = g_h0 + (256 + rb) * HH;
        const float* h2 = g_h0 + (512 + rb) * HH;
#pragma unroll 8
        for (int k = 0; k < HH; ++k) {
            float s = __ldcg(h0 + k) + __ldcg(h1 + k) + __ldcg(h2 + k);
            acc = fmaf(s, Wf[k * OUTF + o], acc);
        }
        out[rb * OUTF + o] = (acc > 0.0f) ? acc : expm1f(acc);
    }
    if (bid < 3) {
        // feature[c][k] = mean_b h[c][b][k]
        int c = bid;
        float acc = 0.0f;
#pragma unroll 8
        for (int b2 = 0; b2 < BB; ++b2)
            acc += __ldcg(&g_h0[(c * 256 + b2) * HH + tid]);
        out[BB * OUTF + c * HH + tid] = acc * (1.0f / 256.0f);
    }
}

// ---------------- launch ----------------
extern "C" void kernel_launch(void* const* d_in, const int* in_sizes, int n_in,
                              void* d_out, int out_size) {
    const float* x   = (const float*)d_in[0];
    const float* hid = (const float*)d_in[1];
    const float* Wx  = (const float*)d_in[2];
    const float* bx  = (const float*)d_in[3];
    const float* Wh  = (const float*)d_in[4];
    const float* bh  = (const float*)d_in[5];
    const float* Wf  = (const float*)d_in[6];
    const float* bf  = (const float*)d_in[7];
    float* out = (float*)d_out;

    const int smem_p = (24576 + RBAND * AP + RBAND * 96) * (int)sizeof(float); // 166656 B
    cudaFuncSetAttribute(cru_persistent, cudaFuncAttributeMaxDynamicSharedMemorySize, smem_p);

    gx_kernel<<<dim3(512, 12), TPB>>>(x, Wx, bx);
    cru_persistent<<<NBLK, TPB, smem_p>>>(hid, Wh, bh, Wf, bf, out);
}